// round 10
// baseline (speedup 1.0000x reference)
#include <cuda_runtime.h>
#include <cuda_bf16.h>
#include <cuda_fp16.h>
#include <cstdint>

#define N_NODES   50000
#define N_EDGES   600000
#define HID       128
#define N_GRAPHS  128
#define N_CLASSES 10

#define SCAN_B    512
#define SCAN_NB   ((N_NODES + SCAN_B - 1) / SCAN_B)    // 98

// ---------------- scratch (no allocation allowed) ----------------
__device__ float  g_h  [(size_t)N_NODES * HID];   // fp32 FC output (pool input)
__device__ __half g_hbA[(size_t)N_NODES * HID];   // fp16 messages, ping
__device__ __half g_hbB[(size_t)N_NODES * HID];   // fp16 messages, pong
__device__ float g_dinv[N_NODES];
__device__ int   g_deg [N_NODES];
__device__ int   g_cur [N_NODES];
__device__ int   g_rowptr[N_NODES + 1];
__device__ int   g_csr_src[N_EDGES];
__device__ int   g_bsum[SCAN_NB];
__device__ float g_pool[N_GRAPHS * HID];
__device__ float g_cnt [N_GRAPHS];
// W in mma.sync B-fragment layout: [layer][term(hi,lo)][kstep][ntile][lane] (b0,b1)
__device__ uint2 g_Bfrag[6][2][8][16][32];

// ---------------- setup kernels ----------------
__global__ void zero_kernel() {
    int i = blockIdx.x * blockDim.x + threadIdx.x;
    if (i < N_NODES)      { g_deg[i] = 0; g_cur[i] = 0; }
    if (i < N_GRAPHS * HID) g_pool[i] = 0.f;
    if (i < N_GRAPHS)       g_cnt[i] = 0.f;
}

__global__ void deg_kernel(const int* __restrict__ ei) {
    int e = blockIdx.x * blockDim.x + threadIdx.x;
    if (e < N_EDGES) atomicAdd(&g_deg[ei[N_EDGES + e]], 1);
}

__global__ void dinv_kernel() {
    int i = blockIdx.x * blockDim.x + threadIdx.x;
    if (i < N_NODES) g_dinv[i] = rsqrtf((float)g_deg[i] + 1.0f);
}

// Build B fragments for all 6 layers in one launch.
struct WPtrs { const float* p[6]; };
__global__ void wprep_kernel(WPtrs wp) {
    int t = blockIdx.x * blockDim.x + threadIdx.x;   // 0..24575
    if (t >= 6 * 8 * 16 * 32) return;
    int l    = t >> 12;         // layer
    int s    = (t >> 9) & 7;    // kstep
    int j    = (t >> 5) & 15;   // ntile
    int lane = t & 31;
    const float* W = wp.p[l];
    int k0 = s * 16 + (lane & 3) * 2;
    int nn = j * 8 + (lane >> 2);
    unsigned hw[2], lw[2];
    #pragma unroll
    for (int q = 0; q < 2; q++) {
        float w0 = W[(k0 + q * 8)     * 128 + nn];
        float w1 = W[(k0 + q * 8 + 1) * 128 + nn];
        __nv_bfloat16 h0 = __float2bfloat16(w0);
        __nv_bfloat16 h1 = __float2bfloat16(w1);
        __nv_bfloat16 l0 = __float2bfloat16(w0 - __bfloat162float(h0));
        __nv_bfloat16 l1 = __float2bfloat16(w1 - __bfloat162float(h1));
        hw[q] = (unsigned)__bfloat16_as_ushort(h0)
              | ((unsigned)__bfloat16_as_ushort(h1) << 16);
        lw[q] = (unsigned)__bfloat16_as_ushort(l0)
              | ((unsigned)__bfloat16_as_ushort(l1) << 16);
    }
    g_Bfrag[l][0][s][j][lane] = make_uint2(hw[0], hw[1]);
    g_Bfrag[l][1][s][j][lane] = make_uint2(lw[0], lw[1]);
}

// ---- decoupled scan ----
__global__ __launch_bounds__(SCAN_B) void scan1_kernel() {
    __shared__ int s[SCAN_B];
    int i = blockIdx.x * SCAN_B + threadIdx.x;
    int v = (i < N_NODES) ? g_deg[i] : 0;
    s[threadIdx.x] = v;
    __syncthreads();
    #pragma unroll
    for (int off = 1; off < SCAN_B; off <<= 1) {
        int t = (threadIdx.x >= off) ? s[threadIdx.x - off] : 0;
        __syncthreads();
        s[threadIdx.x] += t;
        __syncthreads();
    }
    if (i < N_NODES) g_rowptr[i + 1] = s[threadIdx.x];
    if (threadIdx.x == SCAN_B - 1) g_bsum[blockIdx.x] = s[SCAN_B - 1];
}

__global__ void scan2_kernel() {
    __shared__ int s[128];
    int v = (threadIdx.x < SCAN_NB) ? g_bsum[threadIdx.x] : 0;
    s[threadIdx.x] = v;
    __syncthreads();
    #pragma unroll
    for (int off = 1; off < 128; off <<= 1) {
        int t = (threadIdx.x >= off) ? s[threadIdx.x - off] : 0;
        __syncthreads();
        s[threadIdx.x] += t;
        __syncthreads();
    }
    if (threadIdx.x < SCAN_NB) g_bsum[threadIdx.x] = s[threadIdx.x] - v;
}

__global__ void scan3_kernel() {
    int i = blockIdx.x * blockDim.x + threadIdx.x;
    if (i == 0) g_rowptr[0] = 0;
    if (i < N_NODES) g_rowptr[i + 1] += g_bsum[i / SCAN_B];
}

__global__ void place_kernel(const int* __restrict__ ei) {
    int e = blockIdx.x * blockDim.x + threadIdx.x;
    if (e >= N_EDGES) return;
    int r = ei[e];
    int c = ei[N_EDGES + e];
    int pos = g_rowptr[c] + atomicAdd(&g_cur[c], 1);
    g_csr_src[pos] = r;
}

// ---------------- fused gather + mma.sync GEMM ----------------
// Messages double-buffered: layer l reads buf[1-(l&1)], writes buf[l&1]
// (separate launches give the inter-layer barrier; no in-launch RW overlap).
__device__ __forceinline__ void mma_bf16(float* d, const unsigned* a,
                                         const unsigned* b) {
    asm("mma.sync.aligned.m16n8k16.row.col.f32.bf16.bf16.f32 "
        "{%0,%1,%2,%3}, {%4,%5,%6,%7}, {%8,%9}, {%0,%1,%2,%3};"
        : "+f"(d[0]), "+f"(d[1]), "+f"(d[2]), "+f"(d[3])
        : "r"(a[0]), "r"(a[1]), "r"(a[2]), "r"(a[3]), "r"(b[0]), "r"(b[1]));
}

__device__ __forceinline__ float4 h4_to_f4(uint2 u) {
    __half2 a = *(__half2*)&u.x;
    __half2 b = *(__half2*)&u.y;
    float2 fa = __half22float2(a);
    float2 fb = __half22float2(b);
    return make_float4(fa.x, fa.y, fb.x, fb.y);
}

#define A_LD    136                         // padded bf16 row stride
#define SM_AHI  0
#define SM_ALO  (128 * A_LD * 2)            // 34816
#define TC_SMEM (2 * 128 * A_LD * 2)        // 69632

__global__ __launch_bounds__(256, 2) void fused_kernel(
    const float* __restrict__ X, int layer, int n,
    const float* __restrict__ preBias, const float* __restrict__ postBias,
    int outFp16)
{
    extern __shared__ char smem[];
    __nv_bfloat16* ahiS = (__nv_bfloat16*)(smem + SM_AHI);
    __nv_bfloat16* aloS = (__nv_bfloat16*)(smem + SM_ALO);

    const __half* hbIn  = (layer & 1) ? g_hbA : g_hbB;   // buf[1-(l&1)]
    __half*       hbOut = (layer & 1) ? g_hbB : g_hbA;   // buf[l&1]

    int tid  = threadIdx.x;
    int lane = tid & 31;
    int wid  = tid >> 5;
    int row0 = blockIdx.x * 128;

    if (X) {
        // layer 0: A from X, thread-distributed
        #pragma unroll
        for (int it = 0; it < 32; it++) {
            int j = tid + it * 256;          // pair index 0..8191
            int r = j >> 6;
            int c = (j & 63) * 2;
            int row = row0 + r;
            float2 v = make_float2(0.f, 0.f);
            if (row < n) v = *(const float2*)&X[(size_t)row * HID + c];
            __nv_bfloat16 h0 = __float2bfloat16(v.x);
            __nv_bfloat16 h1 = __float2bfloat16(v.y);
            __nv_bfloat16 l0 = __float2bfloat16(v.x - __bfloat162float(h0));
            __nv_bfloat16 l1 = __float2bfloat16(v.y - __bfloat162float(h1));
            *(unsigned*)&ahiS[r * A_LD + c] =
                (unsigned)__bfloat16_as_ushort(h0)
                | ((unsigned)__bfloat16_as_ushort(h1) << 16);
            *(unsigned*)&aloS[r * A_LD + c] =
                (unsigned)__bfloat16_as_ushort(l0)
                | ((unsigned)__bfloat16_as_ushort(l1) << 16);
        }
    } else {
        // gather path: warp per row, lane covers 4 features
        const uint2* hb2 = (const uint2*)hbIn;   // 32 uint2 per row
        float4 pb = ((const float4*)preBias)[lane];
        #pragma unroll 1
        for (int ii = 0; ii < 16; ii++) {
            int r   = wid * 16 + ii;
            int row = row0 + r;
            float4 a = make_float4(0.f, 0.f, 0.f, 0.f);
            if (row < n) {
                float4 acc  = h4_to_f4(hb2[(size_t)row * 32 + lane]); // self
                float4 acc2 = make_float4(0.f, 0.f, 0.f, 0.f);
                int j  = g_rowptr[row];
                int e1 = g_rowptr[row + 1];
                for (; j + 8 <= e1; j += 8) {
                    int s0 = g_csr_src[j];
                    int s1 = g_csr_src[j + 1];
                    int s2 = g_csr_src[j + 2];
                    int s3 = g_csr_src[j + 3];
                    int s4 = g_csr_src[j + 4];
                    int s5 = g_csr_src[j + 5];
                    int s6 = g_csr_src[j + 6];
                    int s7 = g_csr_src[j + 7];
                    float4 v0 = h4_to_f4(hb2[(size_t)s0 * 32 + lane]);
                    float4 v1 = h4_to_f4(hb2[(size_t)s1 * 32 + lane]);
                    float4 v2 = h4_to_f4(hb2[(size_t)s2 * 32 + lane]);
                    float4 v3 = h4_to_f4(hb2[(size_t)s3 * 32 + lane]);
                    float4 v4 = h4_to_f4(hb2[(size_t)s4 * 32 + lane]);
                    float4 v5 = h4_to_f4(hb2[(size_t)s5 * 32 + lane]);
                    float4 v6 = h4_to_f4(hb2[(size_t)s6 * 32 + lane]);
                    float4 v7 = h4_to_f4(hb2[(size_t)s7 * 32 + lane]);
                    acc.x  += (v0.x + v1.x) + (v2.x + v3.x);
                    acc.y  += (v0.y + v1.y) + (v2.y + v3.y);
                    acc.z  += (v0.z + v1.z) + (v2.z + v3.z);
                    acc.w  += (v0.w + v1.w) + (v2.w + v3.w);
                    acc2.x += (v4.x + v5.x) + (v6.x + v7.x);
                    acc2.y += (v4.y + v5.y) + (v6.y + v7.y);
                    acc2.z += (v4.z + v5.z) + (v6.z + v7.z);
                    acc2.w += (v4.w + v5.w) + (v6.w + v7.w);
                }
                if (j + 4 <= e1) {
                    int s0 = g_csr_src[j];
                    int s1 = g_csr_src[j + 1];
                    int s2 = g_csr_src[j + 2];
                    int s3 = g_csr_src[j + 3];
                    float4 v0 = h4_to_f4(hb2[(size_t)s0 * 32 + lane]);
                    float4 v1 = h4_to_f4(hb2[(size_t)s1 * 32 + lane]);
                    float4 v2 = h4_to_f4(hb2[(size_t)s2 * 32 + lane]);
                    float4 v3 = h4_to_f4(hb2[(size_t)s3 * 32 + lane]);
                    acc.x += (v0.x + v1.x) + (v2.x + v3.x);
                    acc.y += (v0.y + v1.y) + (v2.y + v3.y);
                    acc.z += (v0.z + v1.z) + (v2.z + v3.z);
                    acc.w += (v0.w + v1.w) + (v2.w + v3.w);
                    j += 4;
                }
                for (; j < e1; j++) {
                    float4 v = h4_to_f4(hb2[(size_t)g_csr_src[j] * 32 + lane]);
                    acc.x += v.x; acc.y += v.y; acc.z += v.z; acc.w += v.w;
                }
                acc.x += acc2.x; acc.y += acc2.y;
                acc.z += acc2.z; acc.w += acc2.w;
                float d = g_dinv[row];
                a.x = fmaxf(fmaf(acc.x, d, pb.x), 0.f);
                a.y = fmaxf(fmaf(acc.y, d, pb.y), 0.f);
                a.z = fmaxf(fmaf(acc.z, d, pb.z), 0.f);
                a.w = fmaxf(fmaf(acc.w, d, pb.w), 0.f);
            }
            // bf16 hi/lo split, store 4 cols at lane*4
            __nv_bfloat16 h0 = __float2bfloat16(a.x);
            __nv_bfloat16 h1 = __float2bfloat16(a.y);
            __nv_bfloat16 h2 = __float2bfloat16(a.z);
            __nv_bfloat16 h3 = __float2bfloat16(a.w);
            __nv_bfloat16 l0 = __float2bfloat16(a.x - __bfloat162float(h0));
            __nv_bfloat16 l1 = __float2bfloat16(a.y - __bfloat162float(h1));
            __nv_bfloat16 l2 = __float2bfloat16(a.z - __bfloat162float(h2));
            __nv_bfloat16 l3 = __float2bfloat16(a.w - __bfloat162float(h3));
            unsigned hw0 = (unsigned)__bfloat16_as_ushort(h0)
                         | ((unsigned)__bfloat16_as_ushort(h1) << 16);
            unsigned hw1 = (unsigned)__bfloat16_as_ushort(h2)
                         | ((unsigned)__bfloat16_as_ushort(h3) << 16);
            unsigned lw0 = (unsigned)__bfloat16_as_ushort(l0)
                         | ((unsigned)__bfloat16_as_ushort(l1) << 16);
            unsigned lw1 = (unsigned)__bfloat16_as_ushort(l2)
                         | ((unsigned)__bfloat16_as_ushort(l3) << 16);
            *(uint2*)&ahiS[r * A_LD + lane * 4] = make_uint2(hw0, hw1);
            *(uint2*)&aloS[r * A_LD + lane * 4] = make_uint2(lw0, lw1);
        }
    }
    __syncthreads();

    // ---- mma mainloop; B fragments straight from global (L1-hot) ----
    int wm = wid & 3;
    int wn = wid >> 2;
    int rA = wm * 32 + (lane >> 2);
    int cGrp = (lane & 3) * 2;

    float acc[2][8][4];
    #pragma unroll
    for (int i = 0; i < 2; i++)
        #pragma unroll
        for (int j = 0; j < 8; j++)
            #pragma unroll
            for (int q = 0; q < 4; q++) acc[i][j][q] = 0.f;

    const uint2* bfragHi = &g_Bfrag[layer][0][0][0][0];
    const uint2* bfragLo = &g_Bfrag[layer][1][0][0][0];

    #pragma unroll
    for (int s = 0; s < 8; s++) {
        int kc = s * 16 + cGrp;
        unsigned ahi[2][4], alo[2][4];
        #pragma unroll
        for (int i = 0; i < 2; i++) {
            int r = rA + i * 16;
            ahi[i][0] = *(const unsigned*)&ahiS[(r    ) * A_LD + kc    ];
            ahi[i][1] = *(const unsigned*)&ahiS[(r + 8) * A_LD + kc    ];
            ahi[i][2] = *(const unsigned*)&ahiS[(r    ) * A_LD + kc + 8];
            ahi[i][3] = *(const unsigned*)&ahiS[(r + 8) * A_LD + kc + 8];
            alo[i][0] = *(const unsigned*)&aloS[(r    ) * A_LD + kc    ];
            alo[i][1] = *(const unsigned*)&aloS[(r + 8) * A_LD + kc    ];
            alo[i][2] = *(const unsigned*)&aloS[(r    ) * A_LD + kc + 8];
            alo[i][3] = *(const unsigned*)&aloS[(r + 8) * A_LD + kc + 8];
        }
        #pragma unroll
        for (int j = 0; j < 8; j++) {
            int nt = wn * 8 + j;
            uint2 bh = bfragHi[(s * 16 + nt) * 32 + lane];
            uint2 bl = bfragLo[(s * 16 + nt) * 32 + lane];
            #pragma unroll
            for (int i = 0; i < 2; i++) {
                mma_bf16(acc[i][j], ahi[i], (const unsigned*)&bh);
                mma_bf16(acc[i][j], alo[i], (const unsigned*)&bh);
                mma_bf16(acc[i][j], ahi[i], (const unsigned*)&bl);
            }
        }
    }

    // ---- epilogue ----
    #pragma unroll
    for (int i = 0; i < 2; i++) {
        int r0 = row0 + rA + i * 16;
        int r1 = r0 + 8;
        bool ok0 = r0 < n, ok1 = r1 < n;
        if (outFp16) {
            float d0s = ok0 ? g_dinv[r0] : 0.f;
            float d1s = ok1 ? g_dinv[r1] : 0.f;
            #pragma unroll
            for (int j = 0; j < 8; j++) {
                int col = wn * 64 + j * 8 + cGrp;
                if (ok0) {
                    __half2 o = __float22half2_rn(
                        make_float2(acc[i][j][0] * d0s, acc[i][j][1] * d0s));
                    *(__half2*)&hbOut[(size_t)r0 * HID + col] = o;
                }
                if (ok1) {
                    __half2 o = __float22half2_rn(
                        make_float2(acc[i][j][2] * d1s, acc[i][j][3] * d1s));
                    *(__half2*)&hbOut[(size_t)r1 * HID + col] = o;
                }
            }
        } else {
            #pragma unroll
            for (int j = 0; j < 8; j++) {
                int col = wn * 64 + j * 8 + cGrp;
                float b0 = postBias[col], b1 = postBias[col + 1];
                if (ok0) {
                    float2 o;
                    o.x = fmaxf(acc[i][j][0] + b0, 0.f);
                    o.y = fmaxf(acc[i][j][1] + b1, 0.f);
                    *(float2*)&g_h[(size_t)r0 * HID + col] = o;
                }
                if (ok1) {
                    float2 o;
                    o.x = fmaxf(acc[i][j][2] + b0, 0.f);
                    o.y = fmaxf(acc[i][j][3] + b1, 0.f);
                    *(float2*)&g_h[(size_t)r1 * HID + col] = o;
                }
            }
        }
    }
}

// ---------------- global mean pool (batch is sorted) ----------------
#define POOL_CH 128
__global__ void pool_kernel(const int* __restrict__ batch) {
    int t = threadIdx.x;                        // 128: feature column
    int start = blockIdx.x * POOL_CH;
    if (start >= N_NODES) return;
    int end = min(start + POOL_CH, N_NODES);
    int cur = batch[start];
    float acc = 0.f, cnt = 0.f;
    for (int i = start; i < end; i++) {
        int b = batch[i];
        if (b != cur) {
            atomicAdd(&g_pool[cur * HID + t], acc);
            if (t == 0) atomicAdd(&g_cnt[cur], cnt);
            acc = 0.f; cnt = 0.f; cur = b;
        }
        acc += g_h[(size_t)i * HID + t];
        cnt += 1.f;
    }
    atomicAdd(&g_pool[cur * HID + t], acc);
    if (t == 0) atomicAdd(&g_cnt[cur], cnt);
}

// ---------------- final head: mean, embeddings out, logits ----------------
__global__ void final_kernel(const float* __restrict__ Wlin,
                             const float* __restrict__ blin,
                             float* __restrict__ out) {
    int g = blockIdx.x;
    int t = threadIdx.x;
    __shared__ float p[HID];
    float c = fmaxf(g_cnt[g], 1.0f);
    float v = g_pool[g * HID + t] / c;
    out[N_GRAPHS * N_CLASSES + g * HID + t] = v;
    p[t] = v;
    __syncthreads();
    if (t < N_CLASSES) {
        float s = blin[t];
        #pragma unroll 8
        for (int j = 0; j < HID; j++) s += p[j] * Wlin[j * N_CLASSES + t];
        out[g * N_CLASSES + t] = s;
    }
}

// ---------------- launch ----------------
extern "C" void kernel_launch(void* const* d_in, const int* in_sizes, int n_in,
                              void* d_out, int out_size)
{
    const float* x     = (const float*)d_in[0];
    const int*   ei    = (const int*)d_in[1];      // int32 (JAX x64 disabled)
    const int*   batch = (const int*)d_in[2];
    const float* W[6] = {(const float*)d_in[3],  (const float*)d_in[5],
                         (const float*)d_in[7],  (const float*)d_in[9],
                         (const float*)d_in[11], (const float*)d_in[13]};
    const float* b[6] = {(const float*)d_in[4],  (const float*)d_in[6],
                         (const float*)d_in[8],  (const float*)d_in[10],
                         (const float*)d_in[12], (const float*)d_in[14]};
    const float* Wlin = (const float*)d_in[15];
    const float* blin = (const float*)d_in[16];
    float* out = (float*)d_out;

    cudaFuncSetAttribute(fused_kernel,
                         cudaFuncAttributeMaxDynamicSharedMemorySize, TC_SMEM);

    zero_kernel <<<(N_NODES + 255) / 256, 256>>>();
    deg_kernel  <<<(N_EDGES + 255) / 256, 256>>>(ei);
    dinv_kernel <<<(N_NODES + 255) / 256, 256>>>();
    scan1_kernel<<<SCAN_NB, SCAN_B>>>();
    scan2_kernel<<<1, 128>>>();
    scan3_kernel<<<(N_NODES + 255) / 256, 256>>>();
    place_kernel<<<(N_EDGES + 255) / 256, 256>>>(ei);
    WPtrs wp;
    for (int l = 0; l < 6; l++) wp.p[l] = W[l];
    wprep_kernel<<<96, 256>>>(wp);

    const int grid = (N_NODES + 127) / 128;               // 391

    // layer 0: A = x, writes buf0 (l&1 = 0)
    fused_kernel<<<grid, 256, TC_SMEM>>>(x, 0, N_NODES, nullptr, nullptr, 1);
    // layers 1-4: gather buf[1-(l&1)] + relu(+b[l-1]) -> GEMM -> buf[l&1]
    for (int l = 1; l < 5; l++)
        fused_kernel<<<grid, 256, TC_SMEM>>>(nullptr, l, N_NODES, b[l - 1], nullptr, 1);
    // FC (layer 5, odd -> reads buf0): gather + relu(+b4) -> GEMM -> relu(+bfc) fp32
    fused_kernel<<<grid, 256, TC_SMEM>>>(nullptr, 5, N_NODES, b[4], b[5], 0);

    pool_kernel <<<(N_NODES + POOL_CH - 1) / POOL_CH, 128>>>(batch);
    final_kernel<<<N_GRAPHS, 128>>>(Wlin, blin, out);
}

// round 11
// speedup vs baseline: 2.0344x; 2.0344x over previous
#include <cuda_runtime.h>
#include <cuda_bf16.h>
#include <cuda_fp16.h>
#include <cstdint>

#define N_NODES   50000
#define N_EDGES   600000
#define HID       128
#define N_GRAPHS  128
#define N_CLASSES 10

#define SCAN_B    512
#define SCAN_NB   ((N_NODES + SCAN_B - 1) / SCAN_B)    // 98

// ---------------- scratch (no allocation allowed) ----------------
__device__ float  g_h  [(size_t)N_NODES * HID];   // fp32 FC output (pool input)
__device__ float  g_agg[(size_t)N_NODES * HID];   // fp32 aggregation (GEMM input)
__device__ __half g_hbA[(size_t)N_NODES * HID];   // fp16 messages, ping
__device__ __half g_hbB[(size_t)N_NODES * HID];   // fp16 messages, pong
__device__ float g_dinv[N_NODES];
__device__ int   g_deg [N_NODES];
__device__ int   g_cur [N_NODES];
__device__ int   g_rowptr[N_NODES + 1];
__device__ int   g_csr_src[N_EDGES];
__device__ int   g_bsum[SCAN_NB];
__device__ float g_pool[N_GRAPHS * HID];
__device__ float g_cnt [N_GRAPHS];
// W in mma.sync B-fragment layout: [layer][term(hi,lo)][kstep][ntile][lane] (b0,b1)
__device__ uint2 g_Bfrag[6][2][8][16][32];

// ---------------- setup kernels ----------------
__global__ void zero_kernel() {
    int i = blockIdx.x * blockDim.x + threadIdx.x;
    if (i < N_NODES)      { g_deg[i] = 0; g_cur[i] = 0; }
    if (i < N_GRAPHS * HID) g_pool[i] = 0.f;
    if (i < N_GRAPHS)       g_cnt[i] = 0.f;
}

__global__ void deg_kernel(const int* __restrict__ ei) {
    int e = blockIdx.x * blockDim.x + threadIdx.x;
    if (e < N_EDGES) atomicAdd(&g_deg[ei[N_EDGES + e]], 1);
}

__global__ void dinv_kernel() {
    int i = blockIdx.x * blockDim.x + threadIdx.x;
    if (i < N_NODES) g_dinv[i] = rsqrtf((float)g_deg[i] + 1.0f);
}

// Build B fragments for all 6 layers in one launch.
struct WPtrs { const float* p[6]; };
__global__ void wprep_kernel(WPtrs wp) {
    int t = blockIdx.x * blockDim.x + threadIdx.x;   // 0..24575
    if (t >= 6 * 8 * 16 * 32) return;
    int l    = t >> 12;         // layer
    int s    = (t >> 9) & 7;    // kstep
    int j    = (t >> 5) & 15;   // ntile
    int lane = t & 31;
    const float* W = wp.p[l];
    int k0 = s * 16 + (lane & 3) * 2;
    int nn = j * 8 + (lane >> 2);
    unsigned hw[2], lw[2];
    #pragma unroll
    for (int q = 0; q < 2; q++) {
        float w0 = W[(k0 + q * 8)     * 128 + nn];
        float w1 = W[(k0 + q * 8 + 1) * 128 + nn];
        __nv_bfloat16 h0 = __float2bfloat16(w0);
        __nv_bfloat16 h1 = __float2bfloat16(w1);
        __nv_bfloat16 l0 = __float2bfloat16(w0 - __bfloat162float(h0));
        __nv_bfloat16 l1 = __float2bfloat16(w1 - __bfloat162float(h1));
        hw[q] = (unsigned)__bfloat16_as_ushort(h0)
              | ((unsigned)__bfloat16_as_ushort(h1) << 16);
        lw[q] = (unsigned)__bfloat16_as_ushort(l0)
              | ((unsigned)__bfloat16_as_ushort(l1) << 16);
    }
    g_Bfrag[l][0][s][j][lane] = make_uint2(hw[0], hw[1]);
    g_Bfrag[l][1][s][j][lane] = make_uint2(lw[0], lw[1]);
}

// ---- decoupled scan ----
__global__ __launch_bounds__(SCAN_B) void scan1_kernel() {
    __shared__ int s[SCAN_B];
    int i = blockIdx.x * SCAN_B + threadIdx.x;
    int v = (i < N_NODES) ? g_deg[i] : 0;
    s[threadIdx.x] = v;
    __syncthreads();
    #pragma unroll
    for (int off = 1; off < SCAN_B; off <<= 1) {
        int t = (threadIdx.x >= off) ? s[threadIdx.x - off] : 0;
        __syncthreads();
        s[threadIdx.x] += t;
        __syncthreads();
    }
    if (i < N_NODES) g_rowptr[i + 1] = s[threadIdx.x];
    if (threadIdx.x == SCAN_B - 1) g_bsum[blockIdx.x] = s[SCAN_B - 1];
}

__global__ void scan2_kernel() {
    __shared__ int s[128];
    int v = (threadIdx.x < SCAN_NB) ? g_bsum[threadIdx.x] : 0;
    s[threadIdx.x] = v;
    __syncthreads();
    #pragma unroll
    for (int off = 1; off < 128; off <<= 1) {
        int t = (threadIdx.x >= off) ? s[threadIdx.x - off] : 0;
        __syncthreads();
        s[threadIdx.x] += t;
        __syncthreads();
    }
    if (threadIdx.x < SCAN_NB) g_bsum[threadIdx.x] = s[threadIdx.x] - v;
}

__global__ void scan3_kernel() {
    int i = blockIdx.x * blockDim.x + threadIdx.x;
    if (i == 0) g_rowptr[0] = 0;
    if (i < N_NODES) g_rowptr[i + 1] += g_bsum[i / SCAN_B];
}

__global__ void place_kernel(const int* __restrict__ ei) {
    int e = blockIdx.x * blockDim.x + threadIdx.x;
    if (e >= N_EDGES) return;
    int r = ei[e];
    int c = ei[N_EDGES + e];
    int pos = g_rowptr[c] + atomicAdd(&g_cur[c], 1);
    g_csr_src[pos] = r;
}

// ---------------- gather: fp16 messages -> fp32 agg, no atomics ----------
// reads buf written by gemm of layer-1:  (layer&1) ? bufA : bufB
// agg[i] = dinv[i] * ( m[i] + sum_{src in N(i)} m[src] )
__device__ __forceinline__ float4 h4_to_f4(uint2 u) {
    __half2 a = *(__half2*)&u.x;
    __half2 b = *(__half2*)&u.y;
    float2 fa = __half22float2(a);
    float2 fb = __half22float2(b);
    return make_float4(fa.x, fa.y, fb.x, fb.y);
}

__global__ __launch_bounds__(256) void gather_kernel(int layer) {
    int gt   = blockIdx.x * blockDim.x + threadIdx.x;
    int node = gt >> 5;
    int lane = gt & 31;
    if (node >= N_NODES) return;

    const uint2* hb2 = (const uint2*)((layer & 1) ? g_hbA : g_hbB);
    float4 acc  = h4_to_f4(hb2[(size_t)node * 32 + lane]);   // self-loop
    float4 acc2 = make_float4(0.f, 0.f, 0.f, 0.f);
    int j  = g_rowptr[node];
    int e1 = g_rowptr[node + 1];

    for (; j + 8 <= e1; j += 8) {
        int s0 = g_csr_src[j];
        int s1 = g_csr_src[j + 1];
        int s2 = g_csr_src[j + 2];
        int s3 = g_csr_src[j + 3];
        int s4 = g_csr_src[j + 4];
        int s5 = g_csr_src[j + 5];
        int s6 = g_csr_src[j + 6];
        int s7 = g_csr_src[j + 7];
        float4 v0 = h4_to_f4(hb2[(size_t)s0 * 32 + lane]);
        float4 v1 = h4_to_f4(hb2[(size_t)s1 * 32 + lane]);
        float4 v2 = h4_to_f4(hb2[(size_t)s2 * 32 + lane]);
        float4 v3 = h4_to_f4(hb2[(size_t)s3 * 32 + lane]);
        float4 v4 = h4_to_f4(hb2[(size_t)s4 * 32 + lane]);
        float4 v5 = h4_to_f4(hb2[(size_t)s5 * 32 + lane]);
        float4 v6 = h4_to_f4(hb2[(size_t)s6 * 32 + lane]);
        float4 v7 = h4_to_f4(hb2[(size_t)s7 * 32 + lane]);
        acc.x  += (v0.x + v1.x) + (v2.x + v3.x);
        acc.y  += (v0.y + v1.y) + (v2.y + v3.y);
        acc.z  += (v0.z + v1.z) + (v2.z + v3.z);
        acc.w  += (v0.w + v1.w) + (v2.w + v3.w);
        acc2.x += (v4.x + v5.x) + (v6.x + v7.x);
        acc2.y += (v4.y + v5.y) + (v6.y + v7.y);
        acc2.z += (v4.z + v5.z) + (v6.z + v7.z);
        acc2.w += (v4.w + v5.w) + (v6.w + v7.w);
    }
    if (j + 4 <= e1) {
        int s0 = g_csr_src[j];
        int s1 = g_csr_src[j + 1];
        int s2 = g_csr_src[j + 2];
        int s3 = g_csr_src[j + 3];
        float4 v0 = h4_to_f4(hb2[(size_t)s0 * 32 + lane]);
        float4 v1 = h4_to_f4(hb2[(size_t)s1 * 32 + lane]);
        float4 v2 = h4_to_f4(hb2[(size_t)s2 * 32 + lane]);
        float4 v3 = h4_to_f4(hb2[(size_t)s3 * 32 + lane]);
        acc.x += (v0.x + v1.x) + (v2.x + v3.x);
        acc.y += (v0.y + v1.y) + (v2.y + v3.y);
        acc.z += (v0.z + v1.z) + (v2.z + v3.z);
        acc.w += (v0.w + v1.w) + (v2.w + v3.w);
        j += 4;
    }
    for (; j < e1; j++) {
        float4 v = h4_to_f4(hb2[(size_t)g_csr_src[j] * 32 + lane]);
        acc.x += v.x; acc.y += v.y; acc.z += v.z; acc.w += v.w;
    }
    acc.x += acc2.x; acc.y += acc2.y; acc.z += acc2.z; acc.w += acc2.w;
    float d = g_dinv[node];
    acc.x *= d; acc.y *= d; acc.z *= d; acc.w *= d;
    ((float4*)g_agg)[(size_t)node * 32 + lane] = acc;
}

// ---------------- mma.sync GEMM ----------------
// A: X (layer 0) or g_agg (fp32); preBias -> relu(a+b) on load.
// Output: outFp16=1 -> hbOut[row] = half(c*dinv[row]) ; else g_h = relu(c+postBias).
// 3-term bf16 split, B fragments from global (L1-hot).
__device__ __forceinline__ void mma_bf16(float* d, const unsigned* a,
                                         const unsigned* b) {
    asm("mma.sync.aligned.m16n8k16.row.col.f32.bf16.bf16.f32 "
        "{%0,%1,%2,%3}, {%4,%5,%6,%7}, {%8,%9}, {%0,%1,%2,%3};"
        : "+f"(d[0]), "+f"(d[1]), "+f"(d[2]), "+f"(d[3])
        : "r"(a[0]), "r"(a[1]), "r"(a[2]), "r"(a[3]), "r"(b[0]), "r"(b[1]));
}

#define A_LD    136                         // padded bf16 row stride
#define SM_AHI  0
#define SM_ALO  (128 * A_LD * 2)            // 34816
#define TC_SMEM (2 * 128 * A_LD * 2)        // 69632

__global__ __launch_bounds__(256, 2) void gemm_kernel(
    const float* __restrict__ X, int layer, int n,
    const float* __restrict__ preBias, const float* __restrict__ postBias,
    int outFp16)
{
    extern __shared__ char smem[];
    __nv_bfloat16* ahiS = (__nv_bfloat16*)(smem + SM_AHI);
    __nv_bfloat16* aloS = (__nv_bfloat16*)(smem + SM_ALO);

    const float* Ain = X ? X : g_agg;
    __half* hbOut = (layer & 1) ? g_hbB : g_hbA;

    int tid  = threadIdx.x;
    int lane = tid & 31;
    int wid  = tid >> 5;
    int row0 = blockIdx.x * 128;

    // A tile: fp32 (+prebias/relu) -> bf16 hi/lo
    #pragma unroll
    for (int it = 0; it < 32; it++) {
        int j = tid + it * 256;          // pair index 0..8191
        int r = j >> 6;
        int c = (j & 63) * 2;
        int row = row0 + r;
        float2 v = make_float2(0.f, 0.f);
        if (row < n) v = *(const float2*)&Ain[(size_t)row * HID + c];
        if (preBias) {
            v.x = fmaxf(v.x + preBias[c],     0.f);
            v.y = fmaxf(v.y + preBias[c + 1], 0.f);
        }
        __nv_bfloat16 h0 = __float2bfloat16(v.x);
        __nv_bfloat16 h1 = __float2bfloat16(v.y);
        __nv_bfloat16 l0 = __float2bfloat16(v.x - __bfloat162float(h0));
        __nv_bfloat16 l1 = __float2bfloat16(v.y - __bfloat162float(h1));
        *(unsigned*)&ahiS[r * A_LD + c] =
            (unsigned)__bfloat16_as_ushort(h0)
            | ((unsigned)__bfloat16_as_ushort(h1) << 16);
        *(unsigned*)&aloS[r * A_LD + c] =
            (unsigned)__bfloat16_as_ushort(l0)
            | ((unsigned)__bfloat16_as_ushort(l1) << 16);
    }
    __syncthreads();

    // mma mainloop
    int wm = wid & 3;
    int wn = wid >> 2;
    int rA = wm * 32 + (lane >> 2);
    int cGrp = (lane & 3) * 2;

    float acc[2][8][4];
    #pragma unroll
    for (int i = 0; i < 2; i++)
        #pragma unroll
        for (int j = 0; j < 8; j++)
            #pragma unroll
            for (int q = 0; q < 4; q++) acc[i][j][q] = 0.f;

    const uint2* bfragHi = &g_Bfrag[layer][0][0][0][0];
    const uint2* bfragLo = &g_Bfrag[layer][1][0][0][0];

    #pragma unroll
    for (int s = 0; s < 8; s++) {
        int kc = s * 16 + cGrp;
        unsigned ahi[2][4], alo[2][4];
        #pragma unroll
        for (int i = 0; i < 2; i++) {
            int r = rA + i * 16;
            ahi[i][0] = *(const unsigned*)&ahiS[(r    ) * A_LD + kc    ];
            ahi[i][1] = *(const unsigned*)&ahiS[(r + 8) * A_LD + kc    ];
            ahi[i][2] = *(const unsigned*)&ahiS[(r    ) * A_LD + kc + 8];
            ahi[i][3] = *(const unsigned*)&ahiS[(r + 8) * A_LD + kc + 8];
            alo[i][0] = *(const unsigned*)&aloS[(r    ) * A_LD + kc    ];
            alo[i][1] = *(const unsigned*)&aloS[(r + 8) * A_LD + kc    ];
            alo[i][2] = *(const unsigned*)&aloS[(r    ) * A_LD + kc + 8];
            alo[i][3] = *(const unsigned*)&aloS[(r + 8) * A_LD + kc + 8];
        }
        #pragma unroll
        for (int j = 0; j < 8; j++) {
            int nt = wn * 8 + j;
            uint2 bh = bfragHi[(s * 16 + nt) * 32 + lane];
            uint2 bl = bfragLo[(s * 16 + nt) * 32 + lane];
            #pragma unroll
            for (int i = 0; i < 2; i++) {
                mma_bf16(acc[i][j], ahi[i], (const unsigned*)&bh);
                mma_bf16(acc[i][j], alo[i], (const unsigned*)&bh);
                mma_bf16(acc[i][j], ahi[i], (const unsigned*)&bl);
            }
        }
    }

    // epilogue
    #pragma unroll
    for (int i = 0; i < 2; i++) {
        int r0 = row0 + rA + i * 16;
        int r1 = r0 + 8;
        bool ok0 = r0 < n, ok1 = r1 < n;
        if (outFp16) {
            float d0s = ok0 ? g_dinv[r0] : 0.f;
            float d1s = ok1 ? g_dinv[r1] : 0.f;
            #pragma unroll
            for (int j = 0; j < 8; j++) {
                int col = wn * 64 + j * 8 + cGrp;
                if (ok0) {
                    __half2 o = __float22half2_rn(
                        make_float2(acc[i][j][0] * d0s, acc[i][j][1] * d0s));
                    *(__half2*)&hbOut[(size_t)r0 * HID + col] = o;
                }
                if (ok1) {
                    __half2 o = __float22half2_rn(
                        make_float2(acc[i][j][2] * d1s, acc[i][j][3] * d1s));
                    *(__half2*)&hbOut[(size_t)r1 * HID + col] = o;
                }
            }
        } else {
            #pragma unroll
            for (int j = 0; j < 8; j++) {
                int col = wn * 64 + j * 8 + cGrp;
                float b0 = postBias[col], b1 = postBias[col + 1];
                if (ok0) {
                    float2 o;
                    o.x = fmaxf(acc[i][j][0] + b0, 0.f);
                    o.y = fmaxf(acc[i][j][1] + b1, 0.f);
                    *(float2*)&g_h[(size_t)r0 * HID + col] = o;
                }
                if (ok1) {
                    float2 o;
                    o.x = fmaxf(acc[i][j][2] + b0, 0.f);
                    o.y = fmaxf(acc[i][j][3] + b1, 0.f);
                    *(float2*)&g_h[(size_t)r1 * HID + col] = o;
                }
            }
        }
    }
}

// ---------------- global mean pool (batch is sorted) ----------------
#define POOL_CH 128
__global__ void pool_kernel(const int* __restrict__ batch) {
    int t = threadIdx.x;                        // 128: feature column
    int start = blockIdx.x * POOL_CH;
    if (start >= N_NODES) return;
    int end = min(start + POOL_CH, N_NODES);
    int cur = batch[start];
    float acc = 0.f, cnt = 0.f;
    for (int i = start; i < end; i++) {
        int b = batch[i];
        if (b != cur) {
            atomicAdd(&g_pool[cur * HID + t], acc);
            if (t == 0) atomicAdd(&g_cnt[cur], cnt);
            acc = 0.f; cnt = 0.f; cur = b;
        }
        acc += g_h[(size_t)i * HID + t];
        cnt += 1.f;
    }
    atomicAdd(&g_pool[cur * HID + t], acc);
    if (t == 0) atomicAdd(&g_cnt[cur], cnt);
}

// ---------------- final head: mean, embeddings out, logits ----------------
__global__ void final_kernel(const float* __restrict__ Wlin,
                             const float* __restrict__ blin,
                             float* __restrict__ out) {
    int g = blockIdx.x;
    int t = threadIdx.x;
    __shared__ float p[HID];
    float c = fmaxf(g_cnt[g], 1.0f);
    float v = g_pool[g * HID + t] / c;
    out[N_GRAPHS * N_CLASSES + g * HID + t] = v;
    p[t] = v;
    __syncthreads();
    if (t < N_CLASSES) {
        float s = blin[t];
        #pragma unroll 8
        for (int j = 0; j < HID; j++) s += p[j] * Wlin[j * N_CLASSES + t];
        out[g * N_CLASSES + t] = s;
    }
}

// ---------------- launch ----------------
extern "C" void kernel_launch(void* const* d_in, const int* in_sizes, int n_in,
                              void* d_out, int out_size)
{
    const float* x     = (const float*)d_in[0];
    const int*   ei    = (const int*)d_in[1];      // int32 (JAX x64 disabled)
    const int*   batch = (const int*)d_in[2];
    const float* W[6] = {(const float*)d_in[3],  (const float*)d_in[5],
                         (const float*)d_in[7],  (const float*)d_in[9],
                         (const float*)d_in[11], (const float*)d_in[13]};
    const float* b[6] = {(const float*)d_in[4],  (const float*)d_in[6],
                         (const float*)d_in[8],  (const float*)d_in[10],
                         (const float*)d_in[12], (const float*)d_in[14]};
    const float* Wlin = (const float*)d_in[15];
    const float* blin = (const float*)d_in[16];
    float* out = (float*)d_out;

    cudaFuncSetAttribute(gemm_kernel,
                         cudaFuncAttributeMaxDynamicSharedMemorySize, TC_SMEM);

    zero_kernel <<<(N_NODES + 255) / 256, 256>>>();
    deg_kernel  <<<(N_EDGES + 255) / 256, 256>>>(ei);
    dinv_kernel <<<(N_NODES + 255) / 256, 256>>>();
    scan1_kernel<<<SCAN_NB, SCAN_B>>>();
    scan2_kernel<<<1, 128>>>();
    scan3_kernel<<<(N_NODES + 255) / 256, 256>>>();
    place_kernel<<<(N_EDGES + 255) / 256, 256>>>(ei);
    WPtrs wp;
    for (int l = 0; l < 6; l++) wp.p[l] = W[l];
    wprep_kernel<<<96, 256>>>(wp);

    const int gemm_grid   = (N_NODES + 127) / 128;        // 391
    const int gather_grid = (N_NODES * 32 + 255) / 256;   // 6250

    // layer 0: A = x, writes msg buf0 (layer&1==0 -> hbA)
    gemm_kernel<<<gemm_grid, 256, TC_SMEM>>>(x, 0, N_NODES, nullptr, nullptr, 1);
    // layers 1-4: gather (reads buf of layer-1) -> agg ; gemm -> buf[l&1]
    for (int l = 1; l < 5; l++) {
        gather_kernel<<<gather_grid, 256>>>(l);
        gemm_kernel<<<gemm_grid, 256, TC_SMEM>>>(nullptr, l, N_NODES, b[l - 1], nullptr, 1);
    }
    // FC (layer 5): gather reads buf of layer 4 (hbA) -> agg ; gemm -> g_h fp32
    gather_kernel<<<gather_grid, 256>>>(5);
    gemm_kernel<<<gemm_grid, 256, TC_SMEM>>>(nullptr, 5, N_NODES, b[4], b[5], 0);

    pool_kernel <<<(N_NODES + POOL_CH - 1) / POOL_CH, 128>>>(batch);
    final_kernel<<<N_GRAPHS, 128>>>(Wlin, blin, out);
}

// round 12
// speedup vs baseline: 2.1385x; 1.0512x over previous
#include <cuda_runtime.h>
#include <cuda_fp16.h>
#include <cstdint>

#define N_NODES   50000
#define N_EDGES   600000
#define HID       128
#define N_GRAPHS  128
#define N_CLASSES 10

#define SCAN_B    512
#define SCAN_NB   ((N_NODES + SCAN_B - 1) / SCAN_B)    // 98

// ---------------- scratch (no allocation allowed) ----------------
__device__ float  g_h   [(size_t)N_NODES * HID];  // fp32 FC output (pool input)
__device__ __half g_aggH[(size_t)N_NODES * HID];  // fp16 GEMM input (activations)
__device__ __half g_hbA [(size_t)N_NODES * HID];  // fp16 messages, ping
__device__ __half g_hbB [(size_t)N_NODES * HID];  // fp16 messages, pong
__device__ float g_dinv[N_NODES];
__device__ int   g_deg [N_NODES];
__device__ int   g_cur [N_NODES];
__device__ int   g_rowptr[N_NODES + 1];
__device__ int   g_csr_src[N_EDGES];
__device__ int   g_bsum[SCAN_NB];
__device__ float g_pool[N_GRAPHS * HID];
__device__ float g_cnt [N_GRAPHS];
// W in mma.sync B-fragment layout, f16 hi/lo: [layer][term][kstep][ntile][lane]
__device__ uint2 g_Bfrag[6][2][8][16][32];

// ---------------- setup kernels ----------------
__global__ void zero_kernel() {
    int i = blockIdx.x * blockDim.x + threadIdx.x;
    if (i < N_NODES)      { g_deg[i] = 0; g_cur[i] = 0; }
    if (i < N_GRAPHS * HID) g_pool[i] = 0.f;
    if (i < N_GRAPHS)       g_cnt[i] = 0.f;
}

__global__ void deg_kernel(const int* __restrict__ ei) {
    int e = blockIdx.x * blockDim.x + threadIdx.x;
    if (e < N_EDGES) atomicAdd(&g_deg[ei[N_EDGES + e]], 1);
}

__global__ void dinv_kernel() {
    int i = blockIdx.x * blockDim.x + threadIdx.x;
    if (i < N_NODES) g_dinv[i] = rsqrtf((float)g_deg[i] + 1.0f);
}

// Build f16 hi/lo B fragments for all 6 layers in one launch.
struct WPtrs { const float* p[6]; };
__global__ void wprep_kernel(WPtrs wp) {
    int t = blockIdx.x * blockDim.x + threadIdx.x;   // 0..24575
    if (t >= 6 * 8 * 16 * 32) return;
    int l    = t >> 12;
    int s    = (t >> 9) & 7;
    int j    = (t >> 5) & 15;
    int lane = t & 31;
    const float* W = wp.p[l];
    int k0 = s * 16 + (lane & 3) * 2;
    int nn = j * 8 + (lane >> 2);
    unsigned hw[2], lw[2];
    #pragma unroll
    for (int q = 0; q < 2; q++) {
        float w0 = W[(k0 + q * 8)     * 128 + nn];
        float w1 = W[(k0 + q * 8 + 1) * 128 + nn];
        __half h0 = __float2half_rn(w0);
        __half h1 = __float2half_rn(w1);
        __half l0 = __float2half_rn(w0 - __half2float(h0));
        __half l1 = __float2half_rn(w1 - __half2float(h1));
        hw[q] = (unsigned)__half_as_ushort(h0)
              | ((unsigned)__half_as_ushort(h1) << 16);
        lw[q] = (unsigned)__half_as_ushort(l0)
              | ((unsigned)__half_as_ushort(l1) << 16);
    }
    g_Bfrag[l][0][s][j][lane] = make_uint2(hw[0], hw[1]);
    g_Bfrag[l][1][s][j][lane] = make_uint2(lw[0], lw[1]);
}

// layer-0 input: x fp32 -> fp16 activations
__global__ void x2h_kernel(const float* __restrict__ x) {
    int i = blockIdx.x * blockDim.x + threadIdx.x;   // float4 index
    if (i >= N_NODES * 32) return;
    float4 v = ((const float4*)x)[i];
    __half2 a = __float22half2_rn(make_float2(v.x, v.y));
    __half2 b = __float22half2_rn(make_float2(v.z, v.w));
    uint2 o;
    o.x = *(unsigned*)&a;
    o.y = *(unsigned*)&b;
    ((uint2*)g_aggH)[i] = o;
}

// ---- decoupled scan ----
__global__ __launch_bounds__(SCAN_B) void scan1_kernel() {
    __shared__ int s[SCAN_B];
    int i = blockIdx.x * SCAN_B + threadIdx.x;
    int v = (i < N_NODES) ? g_deg[i] : 0;
    s[threadIdx.x] = v;
    __syncthreads();
    #pragma unroll
    for (int off = 1; off < SCAN_B; off <<= 1) {
        int t = (threadIdx.x >= off) ? s[threadIdx.x - off] : 0;
        __syncthreads();
        s[threadIdx.x] += t;
        __syncthreads();
    }
    if (i < N_NODES) g_rowptr[i + 1] = s[threadIdx.x];
    if (threadIdx.x == SCAN_B - 1) g_bsum[blockIdx.x] = s[SCAN_B - 1];
}

__global__ void scan2_kernel() {
    __shared__ int s[128];
    int v = (threadIdx.x < SCAN_NB) ? g_bsum[threadIdx.x] : 0;
    s[threadIdx.x] = v;
    __syncthreads();
    #pragma unroll
    for (int off = 1; off < 128; off <<= 1) {
        int t = (threadIdx.x >= off) ? s[threadIdx.x - off] : 0;
        __syncthreads();
        s[threadIdx.x] += t;
        __syncthreads();
    }
    if (threadIdx.x < SCAN_NB) g_bsum[threadIdx.x] = s[threadIdx.x] - v;
}

__global__ void scan3_kernel() {
    int i = blockIdx.x * blockDim.x + threadIdx.x;
    if (i == 0) g_rowptr[0] = 0;
    if (i < N_NODES) g_rowptr[i + 1] += g_bsum[i / SCAN_B];
}

__global__ void place_kernel(const int* __restrict__ ei) {
    int e = blockIdx.x * blockDim.x + threadIdx.x;
    if (e >= N_EDGES) return;
    int r = ei[e];
    int c = ei[N_EDGES + e];
    int pos = g_rowptr[c] + atomicAdd(&g_cur[c], 1);
    g_csr_src[pos] = r;
}

// ---------------- gather: msgs -> relu(dinv*sum + bias) -> fp16 agg ------
__device__ __forceinline__ float4 h4_to_f4(uint2 u) {
    __half2 a = *(__half2*)&u.x;
    __half2 b = *(__half2*)&u.y;
    float2 fa = __half22float2(a);
    float2 fb = __half22float2(b);
    return make_float4(fa.x, fa.y, fb.x, fb.y);
}

__global__ __launch_bounds__(256) void gather_kernel(
    int layer, const float* __restrict__ bias)
{
    int gt   = blockIdx.x * blockDim.x + threadIdx.x;
    int node = gt >> 5;
    int lane = gt & 31;
    if (node >= N_NODES) return;

    const uint2* hb2 = (const uint2*)((layer & 1) ? g_hbA : g_hbB);
    float4 acc  = h4_to_f4(hb2[(size_t)node * 32 + lane]);   // self-loop
    float4 acc2 = make_float4(0.f, 0.f, 0.f, 0.f);
    int j  = g_rowptr[node];
    int e1 = g_rowptr[node + 1];

    for (; j + 8 <= e1; j += 8) {
        int s0 = g_csr_src[j];
        int s1 = g_csr_src[j + 1];
        int s2 = g_csr_src[j + 2];
        int s3 = g_csr_src[j + 3];
        int s4 = g_csr_src[j + 4];
        int s5 = g_csr_src[j + 5];
        int s6 = g_csr_src[j + 6];
        int s7 = g_csr_src[j + 7];
        float4 v0 = h4_to_f4(hb2[(size_t)s0 * 32 + lane]);
        float4 v1 = h4_to_f4(hb2[(size_t)s1 * 32 + lane]);
        float4 v2 = h4_to_f4(hb2[(size_t)s2 * 32 + lane]);
        float4 v3 = h4_to_f4(hb2[(size_t)s3 * 32 + lane]);
        float4 v4 = h4_to_f4(hb2[(size_t)s4 * 32 + lane]);
        float4 v5 = h4_to_f4(hb2[(size_t)s5 * 32 + lane]);
        float4 v6 = h4_to_f4(hb2[(size_t)s6 * 32 + lane]);
        float4 v7 = h4_to_f4(hb2[(size_t)s7 * 32 + lane]);
        acc.x  += (v0.x + v1.x) + (v2.x + v3.x);
        acc.y  += (v0.y + v1.y) + (v2.y + v3.y);
        acc.z  += (v0.z + v1.z) + (v2.z + v3.z);
        acc.w  += (v0.w + v1.w) + (v2.w + v3.w);
        acc2.x += (v4.x + v5.x) + (v6.x + v7.x);
        acc2.y += (v4.y + v5.y) + (v6.y + v7.y);
        acc2.z += (v4.z + v5.z) + (v6.z + v7.z);
        acc2.w += (v4.w + v5.w) + (v6.w + v7.w);
    }
    if (j + 4 <= e1) {
        int s0 = g_csr_src[j];
        int s1 = g_csr_src[j + 1];
        int s2 = g_csr_src[j + 2];
        int s3 = g_csr_src[j + 3];
        float4 v0 = h4_to_f4(hb2[(size_t)s0 * 32 + lane]);
        float4 v1 = h4_to_f4(hb2[(size_t)s1 * 32 + lane]);
        float4 v2 = h4_to_f4(hb2[(size_t)s2 * 32 + lane]);
        float4 v3 = h4_to_f4(hb2[(size_t)s3 * 32 + lane]);
        acc.x += (v0.x + v1.x) + (v2.x + v3.x);
        acc.y += (v0.y + v1.y) + (v2.y + v3.y);
        acc.z += (v0.z + v1.z) + (v2.z + v3.z);
        acc.w += (v0.w + v1.w) + (v2.w + v3.w);
        j += 4;
    }
    for (; j < e1; j++) {
        float4 v = h4_to_f4(hb2[(size_t)g_csr_src[j] * 32 + lane]);
        acc.x += v.x; acc.y += v.y; acc.z += v.z; acc.w += v.w;
    }
    acc.x += acc2.x; acc.y += acc2.y; acc.z += acc2.z; acc.w += acc2.w;
    float d = g_dinv[node];
    float4 pb = ((const float4*)bias)[lane];
    float4 a;
    a.x = fmaxf(fmaf(acc.x, d, pb.x), 0.f);
    a.y = fmaxf(fmaf(acc.y, d, pb.y), 0.f);
    a.z = fmaxf(fmaf(acc.z, d, pb.z), 0.f);
    a.w = fmaxf(fmaf(acc.w, d, pb.w), 0.f);
    __half2 o0 = __float22half2_rn(make_float2(a.x, a.y));
    __half2 o1 = __float22half2_rn(make_float2(a.z, a.w));
    uint2 o;
    o.x = *(unsigned*)&o0;
    o.y = *(unsigned*)&o1;
    ((uint2*)g_aggH)[(size_t)node * 32 + lane] = o;
}

// ---------------- mma.sync GEMM: 2-term f16 (A exact, W hi/lo) ----------
__device__ __forceinline__ void mma_f16(float* d, const unsigned* a,
                                        const unsigned* b) {
    asm("mma.sync.aligned.m16n8k16.row.col.f32.f16.f16.f32 "
        "{%0,%1,%2,%3}, {%4,%5,%6,%7}, {%8,%9}, {%0,%1,%2,%3};"
        : "+f"(d[0]), "+f"(d[1]), "+f"(d[2]), "+f"(d[3])
        : "r"(a[0]), "r"(a[1]), "r"(a[2]), "r"(a[3]), "r"(b[0]), "r"(b[1]));
}

#define A_LD    136                          // padded f16 row stride
#define TC_SMEM (128 * A_LD * 2)             // 34816 B

__global__ __launch_bounds__(256, 2) void gemm_kernel(
    int layer, int n, const float* __restrict__ postBias, int outFp16)
{
    extern __shared__ char smem[];
    __half* aS = (__half*)smem;

    __half* hbOut = (layer & 1) ? g_hbB : g_hbA;

    int tid  = threadIdx.x;
    int lane = tid & 31;
    int wid  = tid >> 5;
    int row0 = blockIdx.x * 128;

    // A tile: straight fp16 copy (16 uint4 per row)
    {
        const uint4* src = (const uint4*)g_aggH;
        #pragma unroll
        for (int it = 0; it < 8; it++) {
            int j = tid + it * 256;          // 0..2047
            int r = j >> 4;
            int q = j & 15;
            int row = row0 + r;
            uint4 v = make_uint4(0u, 0u, 0u, 0u);
            if (row < n) v = src[(size_t)row * 16 + q];
            *(uint4*)&aS[r * A_LD + q * 8] = v;
        }
    }
    __syncthreads();

    // mma mainloop
    int wm = wid & 3;
    int wn = wid >> 2;
    int rA = wm * 32 + (lane >> 2);
    int cGrp = (lane & 3) * 2;

    float acc[2][8][4];
    #pragma unroll
    for (int i = 0; i < 2; i++)
        #pragma unroll
        for (int j = 0; j < 8; j++)
            #pragma unroll
            for (int q = 0; q < 4; q++) acc[i][j][q] = 0.f;

    const uint2* bfragHi = &g_Bfrag[layer][0][0][0][0];
    const uint2* bfragLo = &g_Bfrag[layer][1][0][0][0];

    #pragma unroll
    for (int s = 0; s < 8; s++) {
        int kc = s * 16 + cGrp;
        unsigned a[2][4];
        #pragma unroll
        for (int i = 0; i < 2; i++) {
            int r = rA + i * 16;
            a[i][0] = *(const unsigned*)&aS[(r    ) * A_LD + kc    ];
            a[i][1] = *(const unsigned*)&aS[(r + 8) * A_LD + kc    ];
            a[i][2] = *(const unsigned*)&aS[(r    ) * A_LD + kc + 8];
            a[i][3] = *(const unsigned*)&aS[(r + 8) * A_LD + kc + 8];
        }
        #pragma unroll
        for (int j = 0; j < 8; j++) {
            int nt = wn * 8 + j;
            uint2 bh = bfragHi[(s * 16 + nt) * 32 + lane];
            uint2 bl = bfragLo[(s * 16 + nt) * 32 + lane];
            #pragma unroll
            for (int i = 0; i < 2; i++) {
                mma_f16(acc[i][j], a[i], (const unsigned*)&bh);
                mma_f16(acc[i][j], a[i], (const unsigned*)&bl);
            }
        }
    }

    // epilogue
    #pragma unroll
    for (int i = 0; i < 2; i++) {
        int r0 = row0 + rA + i * 16;
        int r1 = r0 + 8;
        bool ok0 = r0 < n, ok1 = r1 < n;
        if (outFp16) {
            float d0s = ok0 ? g_dinv[r0] : 0.f;
            float d1s = ok1 ? g_dinv[r1] : 0.f;
            #pragma unroll
            for (int j = 0; j < 8; j++) {
                int col = wn * 64 + j * 8 + cGrp;
                if (ok0) {
                    __half2 o = __float22half2_rn(
                        make_float2(acc[i][j][0] * d0s, acc[i][j][1] * d0s));
                    *(__half2*)&hbOut[(size_t)r0 * HID + col] = o;
                }
                if (ok1) {
                    __half2 o = __float22half2_rn(
                        make_float2(acc[i][j][2] * d1s, acc[i][j][3] * d1s));
                    *(__half2*)&hbOut[(size_t)r1 * HID + col] = o;
                }
            }
        } else {
            #pragma unroll
            for (int j = 0; j < 8; j++) {
                int col = wn * 64 + j * 8 + cGrp;
                float b0 = postBias[col], b1 = postBias[col + 1];
                if (ok0) {
                    float2 o;
                    o.x = fmaxf(acc[i][j][0] + b0, 0.f);
                    o.y = fmaxf(acc[i][j][1] + b1, 0.f);
                    *(float2*)&g_h[(size_t)r0 * HID + col] = o;
                }
                if (ok1) {
                    float2 o;
                    o.x = fmaxf(acc[i][j][2] + b0, 0.f);
                    o.y = fmaxf(acc[i][j][3] + b1, 0.f);
                    *(float2*)&g_h[(size_t)r1 * HID + col] = o;
                }
            }
        }
    }
}

// ---------------- global mean pool (batch is sorted) ----------------
#define POOL_CH 128
__global__ void pool_kernel(const int* __restrict__ batch) {
    int t = threadIdx.x;                        // 128: feature column
    int start = blockIdx.x * POOL_CH;
    if (start >= N_NODES) return;
    int end = min(start + POOL_CH, N_NODES);
    int cur = batch[start];
    float acc = 0.f, cnt = 0.f;
    for (int i = start; i < end; i++) {
        int b = batch[i];
        if (b != cur) {
            atomicAdd(&g_pool[cur * HID + t], acc);
            if (t == 0) atomicAdd(&g_cnt[cur], cnt);
            acc = 0.f; cnt = 0.f; cur = b;
        }
        acc += g_h[(size_t)i * HID + t];
        cnt += 1.f;
    }
    atomicAdd(&g_pool[cur * HID + t], acc);
    if (t == 0) atomicAdd(&g_cnt[cur], cnt);
}

// ---------------- final head: mean, embeddings out, logits ----------------
__global__ void final_kernel(const float* __restrict__ Wlin,
                             const float* __restrict__ blin,
                             float* __restrict__ out) {
    int g = blockIdx.x;
    int t = threadIdx.x;
    __shared__ float p[HID];
    float c = fmaxf(g_cnt[g], 1.0f);
    float v = g_pool[g * HID + t] / c;
    out[N_GRAPHS * N_CLASSES + g * HID + t] = v;
    p[t] = v;
    __syncthreads();
    if (t < N_CLASSES) {
        float s = blin[t];
        #pragma unroll 8
        for (int j = 0; j < HID; j++) s += p[j] * Wlin[j * N_CLASSES + t];
        out[g * N_CLASSES + t] = s;
    }
}

// ---------------- launch ----------------
extern "C" void kernel_launch(void* const* d_in, const int* in_sizes, int n_in,
                              void* d_out, int out_size)
{
    const float* x     = (const float*)d_in[0];
    const int*   ei    = (const int*)d_in[1];      // int32 (JAX x64 disabled)
    const int*   batch = (const int*)d_in[2];
    const float* W[6] = {(const float*)d_in[3],  (const float*)d_in[5],
                         (const float*)d_in[7],  (const float*)d_in[9],
                         (const float*)d_in[11], (const float*)d_in[13]};
    const float* b[6] = {(const float*)d_in[4],  (const float*)d_in[6],
                         (const float*)d_in[8],  (const float*)d_in[10],
                         (const float*)d_in[12], (const float*)d_in[14]};
    const float* Wlin = (const float*)d_in[15];
    const float* blin = (const float*)d_in[16];
    float* out = (float*)d_out;

    cudaFuncSetAttribute(gemm_kernel,
                         cudaFuncAttributeMaxDynamicSharedMemorySize, TC_SMEM);

    zero_kernel <<<(N_NODES + 255) / 256, 256>>>();
    deg_kernel  <<<(N_EDGES + 255) / 256, 256>>>(ei);
    dinv_kernel <<<(N_NODES + 255) / 256, 256>>>();
    scan1_kernel<<<SCAN_NB, SCAN_B>>>();
    scan2_kernel<<<1, 128>>>();
    scan3_kernel<<<(N_NODES + 255) / 256, 256>>>();
    place_kernel<<<(N_EDGES + 255) / 256, 256>>>(ei);
    WPtrs wp;
    for (int l = 0; l < 6; l++) wp.p[l] = W[l];
    wprep_kernel<<<96, 256>>>(wp);

    const int gemm_grid   = (N_NODES + 127) / 128;        // 391
    const int gather_grid = (N_NODES * 32 + 255) / 256;   // 6250

    // layer 0: aggH = fp16(x); gemm writes msg buf A
    x2h_kernel<<<gather_grid, 256>>>(x);
    gemm_kernel<<<gemm_grid, 256, TC_SMEM>>>(0, N_NODES, nullptr, 1);
    // layers 1-4: gather(+bias/relu, fp16 agg) ; gemm -> msg buf
    for (int l = 1; l < 5; l++) {
        gather_kernel<<<gather_grid, 256>>>(l, b[l - 1]);
        gemm_kernel<<<gemm_grid, 256, TC_SMEM>>>(l, N_NODES, nullptr, 1);
    }
    // FC (layer 5): gather(+b4/relu) ; gemm -> relu(+bfc) fp32 g_h
    gather_kernel<<<gather_grid, 256>>>(5, b[4]);
    gemm_kernel<<<gemm_grid, 256, TC_SMEM>>>(5, N_NODES, b[5], 0);

    pool_kernel <<<(N_NODES + POOL_CH - 1) / POOL_CH, 128>>>(batch);
    final_kernel<<<N_GRAPHS, 128>>>(Wlin, blin, out);
}

// round 13
// speedup vs baseline: 2.1724x; 1.0158x over previous
#include <cuda_runtime.h>
#include <cuda_fp16.h>
#include <cstdint>

#define N_NODES   50000
#define N_EDGES   600000
#define HID       128
#define N_GRAPHS  128
#define N_CLASSES 10

#define SCAN_B    512
#define SCAN_NB   ((N_NODES + SCAN_B - 1) / SCAN_B)    // 98

// ---------------- scratch (no allocation allowed) ----------------
__device__ float  g_h   [(size_t)N_NODES * HID];  // fp32 FC output (pool input)
__device__ __half g_aggH[(size_t)N_NODES * HID];  // fp16 GEMM input (activations)
__device__ __half g_hbA [(size_t)N_NODES * HID];  // fp16 messages, ping
__device__ __half g_hbB [(size_t)N_NODES * HID];  // fp16 messages, pong
__device__ float g_dinv[N_NODES];
__device__ int   g_deg [N_NODES];
__device__ int   g_cur [N_NODES];
__device__ int   g_rowptr[N_NODES + 1];
__device__ int   g_csr_src[N_EDGES];
__device__ int   g_bsum[SCAN_NB];
__device__ float g_pool[N_GRAPHS * HID];
__device__ float g_cnt [N_GRAPHS];
// W in mma.sync B-fragment layout, f16 hi/lo: [layer][term][kstep][ntile][lane]
__device__ uint2 g_Bfrag[6][2][8][16][32];

// ---------------- setup kernels ----------------
__global__ void zero_kernel() {
    int i = blockIdx.x * blockDim.x + threadIdx.x;
    if (i < N_NODES)      { g_deg[i] = 0; g_cur[i] = 0; }
    if (i < N_GRAPHS * HID) g_pool[i] = 0.f;
    if (i < N_GRAPHS)       g_cnt[i] = 0.f;
}

__global__ void deg_kernel(const int* __restrict__ ei) {
    int e = blockIdx.x * blockDim.x + threadIdx.x;
    if (e < N_EDGES) atomicAdd(&g_deg[ei[N_EDGES + e]], 1);
}

__global__ void dinv_kernel() {
    int i = blockIdx.x * blockDim.x + threadIdx.x;
    if (i < N_NODES) g_dinv[i] = rsqrtf((float)g_deg[i] + 1.0f);
}

// Build f16 hi/lo B fragments for all 6 layers in one launch.
struct WPtrs { const float* p[6]; };
__global__ void wprep_kernel(WPtrs wp) {
    int t = blockIdx.x * blockDim.x + threadIdx.x;   // 0..24575
    if (t >= 6 * 8 * 16 * 32) return;
    int l    = t >> 12;
    int s    = (t >> 9) & 7;
    int j    = (t >> 5) & 15;
    int lane = t & 31;
    const float* W = wp.p[l];
    int k0 = s * 16 + (lane & 3) * 2;
    int nn = j * 8 + (lane >> 2);
    unsigned hw[2], lw[2];
    #pragma unroll
    for (int q = 0; q < 2; q++) {
        float w0 = W[(k0 + q * 8)     * 128 + nn];
        float w1 = W[(k0 + q * 8 + 1) * 128 + nn];
        __half h0 = __float2half_rn(w0);
        __half h1 = __float2half_rn(w1);
        __half l0 = __float2half_rn(w0 - __half2float(h0));
        __half l1 = __float2half_rn(w1 - __half2float(h1));
        hw[q] = (unsigned)__half_as_ushort(h0)
              | ((unsigned)__half_as_ushort(h1) << 16);
        lw[q] = (unsigned)__half_as_ushort(l0)
              | ((unsigned)__half_as_ushort(l1) << 16);
    }
    g_Bfrag[l][0][s][j][lane] = make_uint2(hw[0], hw[1]);
    g_Bfrag[l][1][s][j][lane] = make_uint2(lw[0], lw[1]);
}

// layer-0 input: x fp32 -> fp16 activations
__global__ void x2h_kernel(const float* __restrict__ x) {
    int i = blockIdx.x * blockDim.x + threadIdx.x;   // float4 index
    if (i >= N_NODES * 32) return;
    float4 v = ((const float4*)x)[i];
    __half2 a = __float22half2_rn(make_float2(v.x, v.y));
    __half2 b = __float22half2_rn(make_float2(v.z, v.w));
    uint2 o;
    o.x = *(unsigned*)&a;
    o.y = *(unsigned*)&b;
    ((uint2*)g_aggH)[i] = o;
}

// ---- decoupled scan ----
__global__ __launch_bounds__(SCAN_B) void scan1_kernel() {
    __shared__ int s[SCAN_B];
    int i = blockIdx.x * SCAN_B + threadIdx.x;
    int v = (i < N_NODES) ? g_deg[i] : 0;
    s[threadIdx.x] = v;
    __syncthreads();
    #pragma unroll
    for (int off = 1; off < SCAN_B; off <<= 1) {
        int t = (threadIdx.x >= off) ? s[threadIdx.x - off] : 0;
        __syncthreads();
        s[threadIdx.x] += t;
        __syncthreads();
    }
    if (i < N_NODES) g_rowptr[i + 1] = s[threadIdx.x];
    if (threadIdx.x == SCAN_B - 1) g_bsum[blockIdx.x] = s[SCAN_B - 1];
}

__global__ void scan2_kernel() {
    __shared__ int s[128];
    int v = (threadIdx.x < SCAN_NB) ? g_bsum[threadIdx.x] : 0;
    s[threadIdx.x] = v;
    __syncthreads();
    #pragma unroll
    for (int off = 1; off < 128; off <<= 1) {
        int t = (threadIdx.x >= off) ? s[threadIdx.x - off] : 0;
        __syncthreads();
        s[threadIdx.x] += t;
        __syncthreads();
    }
    if (threadIdx.x < SCAN_NB) g_bsum[threadIdx.x] = s[threadIdx.x] - v;
}

__global__ void scan3_kernel() {
    int i = blockIdx.x * blockDim.x + threadIdx.x;
    if (i == 0) g_rowptr[0] = 0;
    if (i < N_NODES) g_rowptr[i + 1] += g_bsum[i / SCAN_B];
}

__global__ void place_kernel(const int* __restrict__ ei) {
    int e = blockIdx.x * blockDim.x + threadIdx.x;
    if (e >= N_EDGES) return;
    int r = ei[e];
    int c = ei[N_EDGES + e];
    int pos = g_rowptr[c] + atomicAdd(&g_cur[c], 1);
    g_csr_src[pos] = r;
}

// ---------------- gather: msgs -> relu(dinv*sum + bias) -> fp16 agg ------
__device__ __forceinline__ float4 h4_to_f4(uint2 u) {
    __half2 a = *(__half2*)&u.x;
    __half2 b = *(__half2*)&u.y;
    float2 fa = __half22float2(a);
    float2 fb = __half22float2(b);
    return make_float4(fa.x, fa.y, fb.x, fb.y);
}

__global__ __launch_bounds__(256) void gather_kernel(
    int layer, const float* __restrict__ bias)
{
    int gt   = blockIdx.x * blockDim.x + threadIdx.x;
    int node = gt >> 5;
    int lane = gt & 31;
    if (node >= N_NODES) return;

    const uint2* hb2 = (const uint2*)((layer & 1) ? g_hbA : g_hbB);
    float4 acc  = h4_to_f4(hb2[(size_t)node * 32 + lane]);   // self-loop
    float4 acc2 = make_float4(0.f, 0.f, 0.f, 0.f);
    int j  = g_rowptr[node];
    int e1 = g_rowptr[node + 1];

    for (; j + 8 <= e1; j += 8) {
        int s0 = g_csr_src[j];
        int s1 = g_csr_src[j + 1];
        int s2 = g_csr_src[j + 2];
        int s3 = g_csr_src[j + 3];
        int s4 = g_csr_src[j + 4];
        int s5 = g_csr_src[j + 5];
        int s6 = g_csr_src[j + 6];
        int s7 = g_csr_src[j + 7];
        float4 v0 = h4_to_f4(hb2[(size_t)s0 * 32 + lane]);
        float4 v1 = h4_to_f4(hb2[(size_t)s1 * 32 + lane]);
        float4 v2 = h4_to_f4(hb2[(size_t)s2 * 32 + lane]);
        float4 v3 = h4_to_f4(hb2[(size_t)s3 * 32 + lane]);
        float4 v4 = h4_to_f4(hb2[(size_t)s4 * 32 + lane]);
        float4 v5 = h4_to_f4(hb2[(size_t)s5 * 32 + lane]);
        float4 v6 = h4_to_f4(hb2[(size_t)s6 * 32 + lane]);
        float4 v7 = h4_to_f4(hb2[(size_t)s7 * 32 + lane]);
        acc.x  += (v0.x + v1.x) + (v2.x + v3.x);
        acc.y  += (v0.y + v1.y) + (v2.y + v3.y);
        acc.z  += (v0.z + v1.z) + (v2.z + v3.z);
        acc.w  += (v0.w + v1.w) + (v2.w + v3.w);
        acc2.x += (v4.x + v5.x) + (v6.x + v7.x);
        acc2.y += (v4.y + v5.y) + (v6.y + v7.y);
        acc2.z += (v4.z + v5.z) + (v6.z + v7.z);
        acc2.w += (v4.w + v5.w) + (v6.w + v7.w);
    }
    if (j + 4 <= e1) {
        int s0 = g_csr_src[j];
        int s1 = g_csr_src[j + 1];
        int s2 = g_csr_src[j + 2];
        int s3 = g_csr_src[j + 3];
        float4 v0 = h4_to_f4(hb2[(size_t)s0 * 32 + lane]);
        float4 v1 = h4_to_f4(hb2[(size_t)s1 * 32 + lane]);
        float4 v2 = h4_to_f4(hb2[(size_t)s2 * 32 + lane]);
        float4 v3 = h4_to_f4(hb2[(size_t)s3 * 32 + lane]);
        acc.x += (v0.x + v1.x) + (v2.x + v3.x);
        acc.y += (v0.y + v1.y) + (v2.y + v3.y);
        acc.z += (v0.z + v1.z) + (v2.z + v3.z);
        acc.w += (v0.w + v1.w) + (v2.w + v3.w);
        j += 4;
    }
    for (; j < e1; j++) {
        float4 v = h4_to_f4(hb2[(size_t)g_csr_src[j] * 32 + lane]);
        acc.x += v.x; acc.y += v.y; acc.z += v.z; acc.w += v.w;
    }
    acc.x += acc2.x; acc.y += acc2.y; acc.z += acc2.z; acc.w += acc2.w;
    float d = g_dinv[node];
    float4 pb = ((const float4*)bias)[lane];
    float4 a;
    a.x = fmaxf(fmaf(acc.x, d, pb.x), 0.f);
    a.y = fmaxf(fmaf(acc.y, d, pb.y), 0.f);
    a.z = fmaxf(fmaf(acc.z, d, pb.z), 0.f);
    a.w = fmaxf(fmaf(acc.w, d, pb.w), 0.f);
    __half2 o0 = __float22half2_rn(make_float2(a.x, a.y));
    __half2 o1 = __float22half2_rn(make_float2(a.z, a.w));
    uint2 o;
    o.x = *(unsigned*)&o0;
    o.y = *(unsigned*)&o1;
    ((uint2*)g_aggH)[(size_t)node * 32 + lane] = o;
}

// ---------------- mma.sync GEMM: 2-term f16 (A exact, W hi/lo) ----------
__device__ __forceinline__ void mma_f16(float* d, const unsigned* a,
                                        const unsigned* b) {
    asm("mma.sync.aligned.m16n8k16.row.col.f32.f16.f16.f32 "
        "{%0,%1,%2,%3}, {%4,%5,%6,%7}, {%8,%9}, {%0,%1,%2,%3};"
        : "+f"(d[0]), "+f"(d[1]), "+f"(d[2]), "+f"(d[3])
        : "r"(a[0]), "r"(a[1]), "r"(a[2]), "r"(a[3]), "r"(b[0]), "r"(b[1]));
}

#define A_LD    136                          // padded f16 row stride
#define TC_SMEM (128 * A_LD * 2)             // 34816 B

__global__ __launch_bounds__(256, 2) void gemm_kernel(
    int layer, int n, const float* __restrict__ postBias, int outFp16)
{
    extern __shared__ char smem[];
    __half* aS = (__half*)smem;

    __half* hbOut = (layer & 1) ? g_hbB : g_hbA;

    int tid  = threadIdx.x;
    int lane = tid & 31;
    int wid  = tid >> 5;
    int row0 = blockIdx.x * 128;

    // A tile: straight fp16 copy (16 uint4 per row)
    {
        const uint4* src = (const uint4*)g_aggH;
        #pragma unroll
        for (int it = 0; it < 8; it++) {
            int j = tid + it * 256;          // 0..2047
            int r = j >> 4;
            int q = j & 15;
            int row = row0 + r;
            uint4 v = make_uint4(0u, 0u, 0u, 0u);
            if (row < n) v = src[(size_t)row * 16 + q];
            *(uint4*)&aS[r * A_LD + q * 8] = v;
        }
    }
    __syncthreads();

    // mma mainloop
    int wm = wid & 3;
    int wn = wid >> 2;
    int rA = wm * 32 + (lane >> 2);
    int cGrp = (lane & 3) * 2;

    float acc[2][8][4];
    #pragma unroll
    for (int i = 0; i < 2; i++)
        #pragma unroll
        for (int j = 0; j < 8; j++)
            #pragma unroll
            for (int q = 0; q < 4; q++) acc[i][j][q] = 0.f;

    const uint2* bfragHi = &g_Bfrag[layer][0][0][0][0];
    const uint2* bfragLo = &g_Bfrag[layer][1][0][0][0];

    #pragma unroll
    for (int s = 0; s < 8; s++) {
        int kc = s * 16 + cGrp;
        unsigned a[2][4];
        #pragma unroll
        for (int i = 0; i < 2; i++) {
            int r = rA + i * 16;
            a[i][0] = *(const unsigned*)&aS[(r    ) * A_LD + kc    ];
            a[i][1] = *(const unsigned*)&aS[(r + 8) * A_LD + kc    ];
            a[i][2] = *(const unsigned*)&aS[(r    ) * A_LD + kc + 8];
            a[i][3] = *(const unsigned*)&aS[(r + 8) * A_LD + kc + 8];
        }
        #pragma unroll
        for (int j = 0; j < 8; j++) {
            int nt = wn * 8 + j;
            uint2 bh = bfragHi[(s * 16 + nt) * 32 + lane];
            uint2 bl = bfragLo[(s * 16 + nt) * 32 + lane];
            #pragma unroll
            for (int i = 0; i < 2; i++) {
                mma_f16(acc[i][j], a[i], (const unsigned*)&bh);
                mma_f16(acc[i][j], a[i], (const unsigned*)&bl);
            }
        }
    }

    // epilogue
    #pragma unroll
    for (int i = 0; i < 2; i++) {
        int r0 = row0 + rA + i * 16;
        int r1 = r0 + 8;
        bool ok0 = r0 < n, ok1 = r1 < n;
        if (outFp16) {
            float d0s = ok0 ? g_dinv[r0] : 0.f;
            float d1s = ok1 ? g_dinv[r1] : 0.f;
            #pragma unroll
            for (int j = 0; j < 8; j++) {
                int col = wn * 64 + j * 8 + cGrp;
                if (ok0) {
                    __half2 o = __float22half2_rn(
                        make_float2(acc[i][j][0] * d0s, acc[i][j][1] * d0s));
                    *(__half2*)&hbOut[(size_t)r0 * HID + col] = o;
                }
                if (ok1) {
                    __half2 o = __float22half2_rn(
                        make_float2(acc[i][j][2] * d1s, acc[i][j][3] * d1s));
                    *(__half2*)&hbOut[(size_t)r1 * HID + col] = o;
                }
            }
        } else {
            #pragma unroll
            for (int j = 0; j < 8; j++) {
                int col = wn * 64 + j * 8 + cGrp;
                float b0 = postBias[col], b1 = postBias[col + 1];
                if (ok0) {
                    float2 o;
                    o.x = fmaxf(acc[i][j][0] + b0, 0.f);
                    o.y = fmaxf(acc[i][j][1] + b1, 0.f);
                    *(float2*)&g_h[(size_t)r0 * HID + col] = o;
                }
                if (ok1) {
                    float2 o;
                    o.x = fmaxf(acc[i][j][2] + b0, 0.f);
                    o.y = fmaxf(acc[i][j][3] + b1, 0.f);
                    *(float2*)&g_h[(size_t)r1 * HID + col] = o;
                }
            }
        }
    }
}

// ---------------- global mean pool (batch is sorted) ----------------
#define POOL_CH 128
__global__ void pool_kernel(const int* __restrict__ batch) {
    int t = threadIdx.x;                        // 128: feature column
    int start = blockIdx.x * POOL_CH;
    if (start >= N_NODES) return;
    int end = min(start + POOL_CH, N_NODES);
    int cur = batch[start];
    float acc = 0.f, cnt = 0.f;
    for (int i = start; i < end; i++) {
        int b = batch[i];
        if (b != cur) {
            atomicAdd(&g_pool[cur * HID + t], acc);
            if (t == 0) atomicAdd(&g_cnt[cur], cnt);
            acc = 0.f; cnt = 0.f; cur = b;
        }
        acc += g_h[(size_t)i * HID + t];
        cnt += 1.f;
    }
    atomicAdd(&g_pool[cur * HID + t], acc);
    if (t == 0) atomicAdd(&g_cnt[cur], cnt);
}

// ---------------- final head: mean, embeddings out, logits ----------------
__global__ void final_kernel(const float* __restrict__ Wlin,
                             const float* __restrict__ blin,
                             float* __restrict__ out) {
    int g = blockIdx.x;
    int t = threadIdx.x;
    __shared__ float p[HID];
    float c = fmaxf(g_cnt[g], 1.0f);
    float v = g_pool[g * HID + t] / c;
    out[N_GRAPHS * N_CLASSES + g * HID + t] = v;
    p[t] = v;
    __syncthreads();
    if (t < N_CLASSES) {
        float s = blin[t];
        #pragma unroll 8
        for (int j = 0; j < HID; j++) s += p[j] * Wlin[j * N_CLASSES + t];
        out[g * N_CLASSES + t] = s;
    }
}

// ---------------- launch ----------------
extern "C" void kernel_launch(void* const* d_in, const int* in_sizes, int n_in,
                              void* d_out, int out_size)
{
    const float* x     = (const float*)d_in[0];
    const int*   ei    = (const int*)d_in[1];      // int32 (JAX x64 disabled)
    const int*   batch = (const int*)d_in[2];
    const float* W[6] = {(const float*)d_in[3],  (const float*)d_in[5],
                         (const float*)d_in[7],  (const float*)d_in[9],
                         (const float*)d_in[11], (const float*)d_in[13]};
    const float* b[6] = {(const float*)d_in[4],  (const float*)d_in[6],
                         (const float*)d_in[8],  (const float*)d_in[10],
                         (const float*)d_in[12], (const float*)d_in[14]};
    const float* Wlin = (const float*)d_in[15];
    const float* blin = (const float*)d_in[16];
    float* out = (float*)d_out;

    cudaFuncSetAttribute(gemm_kernel,
                         cudaFuncAttributeMaxDynamicSharedMemorySize, TC_SMEM);

    zero_kernel <<<(N_NODES + 255) / 256, 256>>>();
    deg_kernel  <<<(N_EDGES + 255) / 256, 256>>>(ei);
    dinv_kernel <<<(N_NODES + 255) / 256, 256>>>();
    scan1_kernel<<<SCAN_NB, SCAN_B>>>();
    scan2_kernel<<<1, 128>>>();
    scan3_kernel<<<(N_NODES + 255) / 256, 256>>>();
    place_kernel<<<(N_EDGES + 255) / 256, 256>>>(ei);
    WPtrs wp;
    for (int l = 0; l < 6; l++) wp.p[l] = W[l];
    wprep_kernel<<<96, 256>>>(wp);

    const int gemm_grid   = (N_NODES + 127) / 128;        // 391
    const int gather_grid = (N_NODES * 32 + 255) / 256;   // 6250

    // layer 0: aggH = fp16(x); gemm writes msg buf A
    x2h_kernel<<<gather_grid, 256>>>(x);
    gemm_kernel<<<gemm_grid, 256, TC_SMEM>>>(0, N_NODES, nullptr, 1);
    // layers 1-4: gather(+bias/relu, fp16 agg) ; gemm -> msg buf
    for (int l = 1; l < 5; l++) {
        gather_kernel<<<gather_grid, 256>>>(l, b[l - 1]);
        gemm_kernel<<<gemm_grid, 256, TC_SMEM>>>(l, N_NODES, nullptr, 1);
    }
    // FC (layer 5): gather(+b4/relu) ; gemm -> relu(+bfc) fp32 g_h
    gather_kernel<<<gather_grid, 256>>>(5, b[4]);
    gemm_kernel<<<gemm_grid, 256, TC_SMEM>>>(5, N_NODES, b[5], 0);

    pool_kernel <<<(N_NODES + POOL_CH - 1) / POOL_CH, 128>>>(batch);
    final_kernel<<<N_GRAPHS, 128>>>(Wlin, blin, out);
}